// round 17
// baseline (speedup 1.0000x reference)
#include <cuda_runtime.h>

#define T_STEPS 256
#define NPRE    1024
#define NPOST   1024
#define K       16     // 2^-16 rel truncation; measured rel_err 3.2e-5, 30x under 1e-3
#define TI      64     // rows per CTA tile
#define TJ      128    // cols per CTA tile
#define NTHR    1024

// Single launch, 2-D tiled; CTA (bx,by) owns rows [by*64,..) x cols [bx*128,..).
// e[i][j] = x[i]*q_last[j] - p_last[i]*y[j];  x = sum_k pre[T-K+k][i] * 2^(k-K)
// (TE=1 wipes e history; TP=TN=2 give geometric traces; weights are exact 2^n)
__global__ __launch_bounds__(NTHR, 1)
void stdp_tiled_kernel(const float* __restrict__ pre,
                       const float* __restrict__ post,
                       float* __restrict__ e) {
    __shared__ float s_y[TJ];   // full y trace for tile cols
    __shared__ float s_q[TJ];   // post[T-1][tile cols]
    __shared__ float s_x[TI];   // x trace for tile rows
    __shared__ float s_p[TI];   // pre[T-1][tile rows]

    const int tid = threadIdx.x;
    const int j0  = blockIdx.x * TJ;  // col-tile origin
    const int i0  = blockIdx.y * TI;  // row-tile origin

    if (tid < TJ) {
        // ---- Phase A-y (threads 0..127): one full column trace each.
        //      16 independent loads -> MLP=16, single latency exposure.
        const float* __restrict__ b =
            post + (size_t)(T_STEPS - K) * NPOST + j0 + tid;
        float a0 = 0.0f, a1 = 0.0f, last = 0.0f;
        #pragma unroll
        for (int k = 0; k < K; k += 2) {
            const float v0 = b[(size_t)(k + 0) * NPOST];
            const float v1 = b[(size_t)(k + 1) * NPOST];
            a0 = fmaf(v0, __uint_as_float((unsigned)(127 - K + k + 0) << 23), a0);
            a1 = fmaf(v1, __uint_as_float((unsigned)(127 - K + k + 1) << 23), a1);
            last = v1;                               // k+1 == K-1 survives
        }
        s_y[tid] = a0 + a1;
        s_q[tid] = last;
    } else if (tid >= 512) {
        // ---- Phase A-x (warps 16..31): row r = u>>3, k-slot sub = u&7 ----
        const int u   = tid - 512;
        const int r   = u >> 3;                      // 0..63
        const int sub = u & 7;                       // handles k=sub and k=sub+8
        const float va = pre[(size_t)(T_STEPS - K + sub)     * NPRE + i0 + r];
        const float vb = pre[(size_t)(T_STEPS - K + sub + 8) * NPRE + i0 + r];
        // va*2^(sub-16) + vb*2^(sub-8) = 2^(sub-16)*(va + 256*vb)
        float v = fmaf(256.0f, vb, va)
                  * __uint_as_float((unsigned)(127 - K + sub) << 23);
        #pragma unroll
        for (int o = 4; o; o >>= 1) v += __shfl_xor_sync(0xFFFFFFFFu, v, o);
        if (sub == 0) s_x[r] = v;
        if (sub == 7) s_p[r] = vb;                   // k = 15 is p_last
    }

    __syncthreads();

    // ---- Phase C: thread -> (2 rows, 4 cols); 2 LDS.128 + 2 scalar LDS ----
    const int col4  = tid & 31;                      // local float4 col group
    const int rpair = tid >> 5;                      // 0..31

    const float4 y4 = reinterpret_cast<const float4*>(s_y)[col4];
    const float4 q4 = reinterpret_cast<const float4*>(s_q)[col4];

    float4* __restrict__ out4 =
        reinterpret_cast<float4*>(e) + (size_t)(j0 / 4) + col4;

    #pragma unroll
    for (int rr = 0; rr < 2; rr++) {
        const int r = rpair * 2 + rr;
        const float xi = s_x[r];
        const float pi = s_p[r];
        float4 o;
        o.x = fmaf(xi, q4.x, -pi * y4.x);
        o.y = fmaf(xi, q4.y, -pi * y4.y);
        o.z = fmaf(xi, q4.z, -pi * y4.z);
        o.w = fmaf(xi, q4.w, -pi * y4.w);
        out4[(size_t)(i0 + r) * (NPOST / 4)] = o;
    }
}

extern "C" void kernel_launch(void* const* d_in, const int* in_sizes, int n_in,
                              void* d_out, int out_size) {
    const float* pre  = (const float*)d_in[0];   // [T, NPRE]
    const float* post = (const float*)d_in[1];   // [T, NPOST]
    float* e = (float*)d_out;                    // [NPRE, NPOST]

    dim3 grid(NPOST / TJ, NPRE / TI);            // (8, 16) = 128 CTAs, one wave
    stdp_tiled_kernel<<<grid, NTHR>>>(pre, post, e);
}